// round 15
// baseline (speedup 1.0000x reference)
#include <cuda_runtime.h>
#include <cuda_fp16.h>
#include <cstdint>
#include <math.h>

// ---------------------------------------------------------------------------
// Problem constants
// ---------------------------------------------------------------------------
#define DM    1024
#define DI    2048
#define DS    16
#define DTR   64
#define NB    2
#define LL    2048
#define NTOK  (NB*LL)       // 4096
#define XZC   (2*DI)        // 4096
#define XDBC  (DTR+2*DS)    // 96
#define XPS   8             // x_proj split-K factor
#define NCH   (NB*DI)       // 4096 scan channels
#define CL    128           // scan chunk length
#define NC    (LL/CL)       // 16 chunks

// ---------------------------------------------------------------------------
// Base-ISA helpers (sm_80+; no 'a'-gated instructions)
// ---------------------------------------------------------------------------
__device__ __forceinline__ uint32_t smem_u32(const void* p) {
    uint32_t a;
    asm("{ .reg .u64 t; cvta.to.shared.u64 t, %1; cvt.u32.u64 %0, t; }" : "=r"(a) : "l"(p));
    return a;
}
__device__ __forceinline__ void cp_async16(uint32_t sa, const void* gp) {
    asm volatile("cp.async.cg.shared.global [%0], [%1], 16;" :: "r"(sa), "l"(gp));
}
__device__ __forceinline__ void cp_commit() {
    asm volatile("cp.async.commit_group;" ::: "memory");
}
template<int N>
__device__ __forceinline__ void cp_wait() {
    asm volatile("cp.async.wait_group %0;" :: "n"(N) : "memory");
}
__device__ __forceinline__ void ldsm_x4(uint32_t* r, uint32_t addr) {
    asm volatile("ldmatrix.sync.aligned.m8n8.x4.shared.b16 {%0,%1,%2,%3}, [%4];"
        : "=r"(r[0]), "=r"(r[1]), "=r"(r[2]), "=r"(r[3]) : "r"(addr));
}
__device__ __forceinline__ void mma_fp16(float* c, const uint32_t* a, const uint32_t* b) {
    asm volatile("mma.sync.aligned.m16n8k16.row.col.f32.f16.f16.f32 "
        "{%0,%1,%2,%3},{%4,%5,%6,%7},{%8,%9},{%0,%1,%2,%3};"
        : "+f"(c[0]), "+f"(c[1]), "+f"(c[2]), "+f"(c[3])
        : "r"(a[0]), "r"(a[1]), "r"(a[2]), "r"(a[3]), "r"(b[0]), "r"(b[1]));
}
__device__ __forceinline__ float softplus_f(float v) {
    return (v > 20.f) ? v : log1pf(expf(v));
}
// dA powers: dA[n] = e^(n+1), e = exp(-dl) (fast path when A[n] = -(n+1))
__device__ __forceinline__ void dA_fast(float e, float* dA) {
    float e2 = e * e, e3 = e2 * e, e4 = e2 * e2, e8 = e4 * e4;
    dA[0] = e;        dA[1] = e2;       dA[2] = e3;       dA[3] = e4;
    dA[4] = e4 * e;   dA[5] = e4 * e2;  dA[6] = e4 * e3;  dA[7] = e8;
    dA[8] = e8 * e;   dA[9] = e8 * e2;  dA[10] = e8 * e3; dA[11] = e8 * e4;
    dA[12] = e8 * dA[4]; dA[13] = e8 * dA[5]; dA[14] = e8 * dA[6]; dA[15] = e8 * e8;
}

// ---------------------------------------------------------------------------
// Scratch (device globals)
// ---------------------------------------------------------------------------
__device__ __align__(16) __half g_xnh[(size_t)NTOK*DM];
__device__ __align__(16) __half g_w1h[(size_t)XZC*DM];
__device__ __align__(16) __half g_xz[(size_t)NTOK*XZC];
__device__ __align__(16) __half g_xch[(size_t)NTOK*DI];
__device__ __align__(16) __half g_xpwh[(size_t)XDBC*DI];
__device__ __align__(16) float  g_xdbp[(size_t)XPS*NTOK*XDBC];
__device__ __align__(16) float  g_xdb[(size_t)NTOK*XDBC];
__device__ __align__(16) __half g_dth[(size_t)NTOK*DTR];
__device__ __align__(16) __half g_dtwh[(size_t)DI*DTR];
__device__ __align__(16) __half g_dlh[(size_t)NTOK*DI];
__device__ __align__(16) __half g_ysh[(size_t)NTOK*DI];
__device__ __align__(16) __half g_opwh[(size_t)DM*DI];
__device__ __align__(16) float  g_q[(size_t)NC*NCH*DS];
__device__ __align__(16) float  g_sumdl[(size_t)NC*NCH];
__device__ __align__(16) float  g_hs[(size_t)NC*NCH*DS];

// ---------------------------------------------------------------------------
// Fused f32 -> fp16 convert for all 4 weights (half2 stores)
// ---------------------------------------------------------------------------
#define WN1 (XZC*DM)
#define WN2 (XDBC*DI)
#define WN3 (DI*DTR)
#define WN4 (DM*DI)
__global__ void whalf4_kernel(const float* __restrict__ w1, __half* __restrict__ h1,
                              const float* __restrict__ w2, __half* __restrict__ h2,
                              const float* __restrict__ w3, __half* __restrict__ h3,
                              const float* __restrict__ w4, __half* __restrict__ h4)
{
    int i = (blockIdx.x * 256 + threadIdx.x) * 2;
    const float* w; __half* h; int off;
    if (i < WN1)                 { w = w1; h = h1; off = i; }
    else if (i < WN1+WN2)        { w = w2; h = h2; off = i - WN1; }
    else if (i < WN1+WN2+WN3)    { w = w3; h = h3; off = i - WN1 - WN2; }
    else if (i < WN1+WN2+WN3+WN4){ w = w4; h = h4; off = i - WN1 - WN2 - WN3; }
    else return;
    float2 v = *(const float2*)(w + off);
    *(__half2*)(h + off) = __floats2half2_rn(v.x, v.y);
}

// ---------------------------------------------------------------------------
// LayerNorm -> fp16 (float4 loads, contiguous 4-elem per thread)
// ---------------------------------------------------------------------------
__global__ void ln_kernel(const float* __restrict__ x, const float* __restrict__ w,
                          const float* __restrict__ bb, __half* __restrict__ oh)
{
    int t = blockIdx.x;
    const int d4 = threadIdx.x * 4;
    float4 v = *(const float4*)(x + (size_t)t * DM + d4);
    float s  = v.x + v.y + v.z + v.w;
    float s2 = v.x * v.x + v.y * v.y + v.z * v.z + v.w * v.w;
#pragma unroll
    for (int o = 16; o > 0; o >>= 1) {
        s  += __shfl_xor_sync(0xffffffffu, s,  o);
        s2 += __shfl_xor_sync(0xffffffffu, s2, o);
    }
    __shared__ float rs[8], rs2[8];
    int wid = threadIdx.x >> 5, lid = threadIdx.x & 31;
    if (lid == 0) { rs[wid] = s; rs2[wid] = s2; }
    __syncthreads();
    if (wid == 0) {
        float a  = (lid < 8) ? rs[lid]  : 0.f;
        float a2 = (lid < 8) ? rs2[lid] : 0.f;
#pragma unroll
        for (int o = 4; o > 0; o >>= 1) {
            a  += __shfl_xor_sync(0xffffffffu, a,  o);
            a2 += __shfl_xor_sync(0xffffffffu, a2, o);
        }
        if (lid == 0) { rs[0] = a; rs2[0] = a2; }
    }
    __syncthreads();
    float mu = rs[0] * (1.f / DM);
    float var = rs2[0] * (1.f / DM) - mu * mu;
    float rstd = rsqrtf(var + 1e-5f);
    float4 wv = *(const float4*)(w + d4);
    float4 bv = *(const float4*)(bb + d4);
    float y0 = (v.x - mu) * rstd * wv.x + bv.x;
    float y1 = (v.y - mu) * rstd * wv.y + bv.y;
    float y2 = (v.z - mu) * rstd * wv.z + bv.z;
    float y3 = (v.w - mu) * rstd * wv.w + bv.w;
    __half2* op = (__half2*)(oh + (size_t)t * DM + d4);
    op[0] = __floats2half2_rn(y0, y1);
    op[1] = __floats2half2_rn(y2, y3);
}

// ---------------------------------------------------------------------------
// fp16 HMMA GEMM: CTA 128 x BN (BN = NWN*32), warp tile 64x32, K-chunks 64,
// triple-buffered cp.async, SMEM rows 144 B, B via ldsm_x4 pairs.
// Optional split-K via gridDim.z.
// EPI: 0 plain f32, 2 +resid f32, 4 fp16 out, 5 softplus(+bias) fp16 out
// ---------------------------------------------------------------------------
template<int NWN, int EPI>
__global__ void __launch_bounds__(64 * NWN, 2) hmma_gemm(
    int M, int N, int Ktot, int Kper,
    const __half* __restrict__ A, const __half* __restrict__ B,
    float* __restrict__ C, int ldc,
    const float* __restrict__ bias,
    const float* __restrict__ resid, int ldr)
{
    constexpr int BN      = NWN * 32;
    constexpr int THREADS = 64 * NWN;
    constexpr int RSTRIDE = 144;
    constexpr int AB      = 128 * RSTRIDE;
    constexpr int BB      = BN * RSTRIDE;
    constexpr int BUF     = AB + BB;

    extern __shared__ char smraw[];
    const uint32_t sbase = smem_u32(smraw);

    const int tid  = threadIdx.x;
    const int lane = tid & 31;
    const int wid  = tid >> 5;
    const int warp_m = wid / NWN;
    const int warp_n = wid % NWN;
    const int bm = blockIdx.y * 128;
    const int bn = blockIdx.x * BN;
    const int kbase = blockIdx.z * Kper;
    const int KC = Kper >> 6;
    float* Cz = C + (size_t)blockIdx.z * M * ldc;

    float acc[4][4][4];
#pragma unroll
    for (int i = 0; i < 4; i++)
#pragma unroll
        for (int j = 0; j < 4; j++)
#pragma unroll
            for (int q = 0; q < 4; q++) acc[i][j][q] = 0.f;

    auto load_chunk = [&](int c, int b) {
        const int koff = kbase + c * 64;
        const uint32_t bbase = sbase + (uint32_t)b * BUF;
        for (int i = tid; i < 1024; i += THREADS) {          // A: 128 rows x 8 segs
            int row = i >> 3, seg = i & 7;
            cp_async16(bbase + row * RSTRIDE + seg * 16,
                       A + (size_t)(bm + row) * Ktot + koff + seg * 8);
        }
        for (int i = tid; i < BN * 8; i += THREADS) {        // B: BN rows x 8 segs
            int row = i >> 3, seg = i & 7;
            cp_async16(bbase + AB + row * RSTRIDE + seg * 16,
                       B + (size_t)(bn + row) * Ktot + koff + seg * 8);
        }
        cp_commit();
    };

    load_chunk(0, 0);
    if (KC > 1) load_chunk(1, 1);

    for (int c = 0; c < KC; c++) {
        if (c + 2 < KC) { load_chunk(c + 2, (c + 2) % 3); cp_wait<2>(); }
        else if (c + 1 < KC) { cp_wait<1>(); }
        else { cp_wait<0>(); }
        __syncthreads();

        const uint32_t bbase = sbase + (uint32_t)(c % 3) * BUF;
#pragma unroll
        for (int ks = 0; ks < 4; ks++) {
            uint32_t ah[4][4], bh[4][2];
            const uint32_t a_lane = (uint32_t)((warp_m * 64 + (lane & 15)) * RSTRIDE
                                               + ks * 32 + (lane >> 4) * 16);
#pragma unroll
            for (int mi = 0; mi < 4; mi++)
                ldsm_x4(ah[mi], bbase + a_lane + mi * 16 * RSTRIDE);
            // B: one ldsm_x4 covers two n8 tiles (lanes 16-31 -> rows +8)
            const uint32_t b_lane = (uint32_t)((warp_n * 32 + ((lane >> 4) & 1) * 8 + (lane & 7)) * RSTRIDE
                                               + ks * 32 + ((lane >> 3) & 1) * 16);
#pragma unroll
            for (int nj = 0; nj < 2; nj++) {
                uint32_t r4[4];
                ldsm_x4(r4, bbase + AB + b_lane + nj * 16 * RSTRIDE);
                bh[2 * nj][0] = r4[0]; bh[2 * nj][1] = r4[1];
                bh[2 * nj + 1][0] = r4[2]; bh[2 * nj + 1][1] = r4[3];
            }
#pragma unroll
            for (int mi = 0; mi < 4; mi++)
#pragma unroll
                for (int ni = 0; ni < 4; ni++)
                    mma_fp16(acc[mi][ni], ah[mi], bh[ni]);
        }
        __syncthreads();
    }

#pragma unroll
    for (int mi = 0; mi < 4; mi++)
#pragma unroll
        for (int ni = 0; ni < 4; ni++) {
            float* cc = acc[mi][ni];
            const int m0 = bm + warp_m * 64 + mi * 16 + (lane >> 2);
            const int n0 = bn + warp_n * 32 + ni * 8 + (lane & 3) * 2;
#pragma unroll
            for (int half = 0; half < 2; half++) {
                const int m = m0 + half * 8;
                float v0 = cc[half * 2], v1 = cc[half * 2 + 1];
                if (EPI == 5) { v0 = softplus_f(v0 + bias[n0]); v1 = softplus_f(v1 + bias[n0 + 1]); }
                if (EPI == 2) {
                    const float2 r2 = *(const float2*)(resid + (size_t)m * ldr + n0);
                    v0 += r2.x; v1 += r2.y;
                }
                if (EPI == 4 || EPI == 5) {
                    __half* Ch = (__half*)Cz;
                    *(__half2*)(Ch + (size_t)m * ldc + n0) = __floats2half2_rn(v0, v1);
                } else {
                    *(float2*)(Cz + (size_t)m * ldc + n0) = make_float2(v0, v1);
                }
            }
        }
}

// ---------------------------------------------------------------------------
// x_proj split-K reduce: xdb = sum_z partials; also emit dt (cols 0..63) fp16
// ---------------------------------------------------------------------------
__global__ void xdb_reduce_kernel(const float* __restrict__ part, float* __restrict__ xdb,
                                  __half* __restrict__ dth)
{
    int idx = blockIdx.x * 256 + threadIdx.x;
    if (idx >= NTOK * XDBC) return;
    float s = 0.f;
#pragma unroll
    for (int z = 0; z < XPS; z++) s += part[(size_t)z * NTOK * XDBC + idx];
    xdb[idx] = s;
    int n = idx % XDBC;
    if (n < DTR) {
        int m = idx / XDBC;
        dth[(size_t)m * DTR + n] = __float2half_rn(s);
    }
}

// ---------------------------------------------------------------------------
// Depthwise causal conv (k=4) + bias + SiLU.
// Each thread: 2 adjacent channels x 8 consecutive timesteps -> 11 half2
// loads produce 8 half2 outputs (1.375 loads/output).
// ---------------------------------------------------------------------------
__global__ void conv_silu_kernel(const __half* __restrict__ xz, const float* __restrict__ cw,
                                 const float* __restrict__ cb, __half* __restrict__ oh)
{
    int idx = blockIdx.x * blockDim.x + threadIdx.x;   // NTOK*DI/16 threads
    int dp = idx & (DI / 2 - 1);
    int d  = dp * 2;
    int tg = idx >> 10;
    int t0 = (tg & (LL / 8 - 1)) * 8;
    int b  = tg >> 8;                                  // LL/8 = 256

    float4 wa = *(const float4*)(cw + d * 4);
    float4 wb = *(const float4*)(cw + d * 4 + 4);
    float2 bias2 = *(const float2*)(cb + d);

    const __half* col = xz + (size_t)b * LL * XZC + d;
    float2 v[11];
#pragma unroll
    for (int k = 0; k < 11; k++) {
        int t = t0 + k - 3;
        v[k] = (t >= 0) ? __half22float2(*(const __half2*)(col + (size_t)t * XZC))
                        : make_float2(0.f, 0.f);
    }
#pragma unroll
    for (int i = 0; i < 8; i++) {
        float a0 = bias2.x, a1 = bias2.y;
        a0 = fmaf(v[i].x,     wa.x, a0); a1 = fmaf(v[i].y,     wb.x, a1);
        a0 = fmaf(v[i + 1].x, wa.y, a0); a1 = fmaf(v[i + 1].y, wb.y, a1);
        a0 = fmaf(v[i + 2].x, wa.z, a0); a1 = fmaf(v[i + 2].y, wb.z, a1);
        a0 = fmaf(v[i + 3].x, wa.w, a0); a1 = fmaf(v[i + 3].y, wb.w, a1);
        float r0 = a0 * __fdividef(1.f, 1.f + __expf(-a0));
        float r1 = a1 * __fdividef(1.f, 1.f + __expf(-a1));
        *(__half2*)(oh + ((size_t)b * LL + t0 + i) * DI + d) = __floats2half2_rn(r0, r1);
    }
}

// ---------------------------------------------------------------------------
// Chunked scan, phase A: per chunk, local scan with h0=0 -> q, sum(delta).
// ---------------------------------------------------------------------------
__global__ void __launch_bounds__(128) scanA_kernel(
    const __half* __restrict__ delta, const __half* __restrict__ u,
    const float* __restrict__ xdb, const float* __restrict__ A_log,
    float* __restrict__ q, float* __restrict__ sumdl)
{
    const int tc = blockIdx.x & 15;
    const int g  = blockIdx.x >> 4;
    const int b  = g >> 4;
    const int d0 = (g & 15) << 7;
    const int tid = threadIdx.x;
    const int d = d0 + tid;

    float An[DS];
    bool fast = true;
#pragma unroll
    for (int n = 0; n < DS; n++) {
        An[n] = -expf(A_log[d * DS + n]);
        fast = fast && (fabsf(An[n] + (float)(n + 1)) < 1e-4f * (float)(n + 1));
    }
    float h[DS];
#pragma unroll
    for (int n = 0; n < DS; n++) h[n] = 0.f;
    float sdl = 0.f;

    const size_t base_u  = (size_t)b * LL * DI + d0 + tid;
    const size_t base_bc = (size_t)b * LL * XDBC + DTR;
    const int t0 = tc * CL;

    __shared__ float sB[32][DS];
    for (int tile = 0; tile < CL / 32; tile++) {
        __syncthreads();
        for (int i = tid; i < 32 * DS; i += 128) {
            int s = i >> 4, j = i & 15;
            sB[s][j] = xdb[base_bc + (size_t)(t0 + tile * 32 + s) * XDBC + j];
        }
        __syncthreads();
#pragma unroll 2
        for (int s = 0; s < 32; s++) {
            const int t = t0 + tile * 32 + s;
            float dl = __half2float(delta[base_u + (size_t)t * DI]);
            float ut = __half2float(u[base_u + (size_t)t * DI]);
            sdl += dl;
            float dA[DS];
            if (fast) { dA_fast(__expf(-dl), dA); }
            else {
#pragma unroll
                for (int n = 0; n < DS; n++) dA[n] = __expf(dl * An[n]);
            }
            float w = dl * ut;
#pragma unroll
            for (int n = 0; n < DS; n++)
                h[n] = fmaf(dA[n], h[n], w * sB[s][n]);
        }
    }
    const int bd = b * DI + d;
    float* qp = q + ((size_t)tc * NCH + bd) * DS;
#pragma unroll
    for (int n = 0; n < DS; n += 4)
        *(float4*)(qp + n) = make_float4(h[n], h[n + 1], h[n + 2], h[n + 3]);
    sumdl[tc * NCH + bd] = sdl;
}

// ---------------------------------------------------------------------------
// Chunked scan, phase B: serial prefix over 16 chunks -> h_start per chunk.
// ---------------------------------------------------------------------------
__global__ void __launch_bounds__(128) scanB_kernel(
    const float* __restrict__ q, const float* __restrict__ sumdl,
    const float* __restrict__ A_log, float* __restrict__ hs)
{
    const int bd = blockIdx.x * 128 + threadIdx.x;
    const int d = bd & (DI - 1);

    float An[DS];
    bool fast = true;
#pragma unroll
    for (int n = 0; n < DS; n++) {
        An[n] = -expf(A_log[d * DS + n]);
        fast = fast && (fabsf(An[n] + (float)(n + 1)) < 1e-4f * (float)(n + 1));
    }
    float h[DS];
#pragma unroll
    for (int n = 0; n < DS; n++) h[n] = 0.f;

    for (int c = 0; c < NC; c++) {
        float* hp = hs + ((size_t)c * NCH + bd) * DS;
#pragma unroll
        for (int n = 0; n < DS; n += 4)
            *(float4*)(hp + n) = make_float4(h[n], h[n + 1], h[n + 2], h[n + 3]);
        if (c == NC - 1) break;
        float sdl = sumdl[c * NCH + bd];
        float P[DS];
        if (fast) { dA_fast(__expf(-sdl), P); }
        else {
#pragma unroll
            for (int n = 0; n < DS; n++) P[n] = __expf(An[n] * sdl);
        }
        const float* qp = q + ((size_t)c * NCH + bd) * DS;
#pragma unroll
        for (int n = 0; n < DS; n++)
            h[n] = fmaf(P[n], h[n], qp[n]);
    }
}

// ---------------------------------------------------------------------------
// Chunked scan, phase C: re-scan with correct h_start, gate with silu(z).
// ---------------------------------------------------------------------------
__global__ void __launch_bounds__(128) scanC_kernel(
    const __half* __restrict__ delta, const __half* __restrict__ u,
    const __half* __restrict__ xz, const float* __restrict__ xdb,
    const float* __restrict__ A_log, const float* __restrict__ Dp,
    const float* __restrict__ hs, __half* __restrict__ ysh)
{
    const int tc = blockIdx.x & 15;
    const int g  = blockIdx.x >> 4;
    const int b  = g >> 4;
    const int d0 = (g & 15) << 7;
    const int tid = threadIdx.x;
    const int d = d0 + tid;

    float An[DS];
    bool fast = true;
#pragma unroll
    for (int n = 0; n < DS; n++) {
        An[n] = -expf(A_log[d * DS + n]);
        fast = fast && (fabsf(An[n] + (float)(n + 1)) < 1e-4f * (float)(n + 1));
    }
    float Dd = Dp[d];
    const int bd = b * DI + d;
    float h[DS];
    {
        const float* hp = hs + ((size_t)tc * NCH + bd) * DS;
#pragma unroll
        for (int n = 0; n < DS; n += 4) {
            float4 v = *(const float4*)(hp + n);
            h[n] = v.x; h[n + 1] = v.y; h[n + 2] = v.z; h[n + 3] = v.w;
        }
    }

    const size_t base_u  = (size_t)b * LL * DI + d0 + tid;
    const size_t base_z  = (size_t)b * LL * XZC + DI + d0 + tid;
    const size_t base_bc = (size_t)b * LL * XDBC + DTR;
    const int t0 = tc * CL;

    __shared__ float sBC[32][2 * DS];
    for (int tile = 0; tile < CL / 32; tile++) {
        __syncthreads();
        for (int i = tid; i < 32 * 2 * DS; i += 128) {
            int s = i >> 5, j = i & 31;
            sBC[s][j] = xdb[base_bc + (size_t)(t0 + tile * 32 + s) * XDBC + j];
        }
        __syncthreads();
#pragma unroll 2
        for (int s = 0; s < 32; s++) {
            const int t = t0 + tile * 32 + s;
            float dl = __half2float(delta[base_u + (size_t)t * DI]);
            float ut = __half2float(u[base_u + (size_t)t * DI]);
            float zt = __half2float(xz[base_z + (size_t)t * XZC]);
            float dA[DS];
            if (fast) { dA_fast(__expf(-dl), dA); }
            else {
#pragma unroll
                for (int n = 0; n < DS; n++) dA[n] = __expf(dl * An[n]);
            }
            float w = dl * ut;
#pragma unroll
            for (int n = 0; n < DS; n++)
                h[n] = fmaf(dA[n], h[n], w * sBC[s][n]);

            float y0 = 0.f, y1 = 0.f, y2 = 0.f, y3 = 0.f;
#pragma unroll
            for (int n = 0; n < DS; n += 4) {
                y0 = fmaf(h[n],     sBC[s][DS + n],     y0);
                y1 = fmaf(h[n + 1], sBC[s][DS + n + 1], y1);
                y2 = fmaf(h[n + 2], sBC[s][DS + n + 2], y2);
                y3 = fmaf(h[n + 3], sBC[s][DS + n + 3], y3);
            }
            float y = (y0 + y1) + (y2 + y3) + ut * Dd;
            float sig = __fdividef(1.f, 1.f + __expf(-zt));
            ysh[base_u + (size_t)t * DI] = __float2half_rn(y * zt * sig);
        }
    }
}

// ---------------------------------------------------------------------------
// Launch sequence
// ---------------------------------------------------------------------------
static inline int gemm_smem(int BN) { return 3 * (128 + BN) * 144; }

extern "C" void kernel_launch(void* const* d_in, const int* in_sizes, int n_in,
                              void* d_out, int out_size)
{
    const float* x         = (const float*)d_in[0];
    const float* norm_w    = (const float*)d_in[1];
    const float* norm_b    = (const float*)d_in[2];
    const float* in_proj_w = (const float*)d_in[3];
    const float* conv_w    = (const float*)d_in[4];
    const float* conv_b    = (const float*)d_in[5];
    const float* x_proj_w  = (const float*)d_in[6];
    const float* dt_proj_w = (const float*)d_in[7];
    const float* dt_proj_b = (const float*)d_in[8];
    const float* A_log     = (const float*)d_in[9];
    const float* D_param   = (const float*)d_in[10];
    const float* out_proj_w= (const float*)d_in[11];
    float* out = (float*)d_out;

    __half *xnh, *w1h, *xzh, *xch, *xpwh, *dth, *dtwh, *dlh, *ysh, *opwh;
    float *xdbp, *xdb, *qb, *sumdlb, *hsb;
    cudaGetSymbolAddress((void**)&xnh, g_xnh);
    cudaGetSymbolAddress((void**)&w1h, g_w1h);
    cudaGetSymbolAddress((void**)&xzh, g_xz);
    cudaGetSymbolAddress((void**)&xch, g_xch);
    cudaGetSymbolAddress((void**)&xpwh, g_xpwh);
    cudaGetSymbolAddress((void**)&xdbp, g_xdbp);
    cudaGetSymbolAddress((void**)&xdb, g_xdb);
    cudaGetSymbolAddress((void**)&dth, g_dth);
    cudaGetSymbolAddress((void**)&dtwh, g_dtwh);
    cudaGetSymbolAddress((void**)&dlh, g_dlh);
    cudaGetSymbolAddress((void**)&ysh, g_ysh);
    cudaGetSymbolAddress((void**)&opwh, g_opwh);
    cudaGetSymbolAddress((void**)&qb, g_q);
    cudaGetSymbolAddress((void**)&sumdlb, g_sumdl);
    cudaGetSymbolAddress((void**)&hsb, g_hs);

    cudaFuncSetAttribute(hmma_gemm<4, 4>, cudaFuncAttributeMaxDynamicSharedMemorySize, gemm_smem(128));
    cudaFuncSetAttribute(hmma_gemm<4, 5>, cudaFuncAttributeMaxDynamicSharedMemorySize, gemm_smem(128));
    cudaFuncSetAttribute(hmma_gemm<2, 2>, cudaFuncAttributeMaxDynamicSharedMemorySize, gemm_smem(64));
    cudaFuncSetAttribute(hmma_gemm<3, 0>, cudaFuncAttributeMaxDynamicSharedMemorySize, gemm_smem(96));

    // fused weight converts
    {
        int pairs = (WN1 + WN2 + WN3 + WN4) / 2;
        whalf4_kernel<<<(pairs + 255) / 256, 256>>>(in_proj_w, w1h, x_proj_w, xpwh,
                                                    dt_proj_w, dtwh, out_proj_w, opwh);
    }

    // 1) LayerNorm -> xn fp16
    ln_kernel<<<NTOK, 256>>>(x, norm_w, norm_b, xnh);

    // 2) in_proj: xz(fp16)[4096,4096] = xn @ in_proj_w^T (R12 config: BN=128)
    hmma_gemm<4, 4><<<dim3(XZC / 128, NTOK / 128), 256, gemm_smem(128)>>>(
        NTOK, XZC, DM, DM, xnh, w1h, (float*)xzh, XZC, nullptr, nullptr, 0);

    // 3) conv + SiLU -> xch fp16 (2 channels x 8 timesteps per thread)
    conv_silu_kernel<<<(NTOK * DI / 16) / 256, 256>>>(xzh, conv_w, conv_b, xch);

    // 4) x_proj (split-K x8): partials, then reduce (+ dt fp16)
    hmma_gemm<3, 0><<<dim3(1, NTOK / 128, XPS), 192, gemm_smem(96)>>>(
        NTOK, XDBC, DI, DI / XPS, xch, xpwh, xdbp, XDBC, nullptr, nullptr, 0);
    xdb_reduce_kernel<<<(NTOK * XDBC + 255) / 256, 256>>>(xdbp, xdb, dth);

    // 5) dt_proj + softplus -> delta fp16
    hmma_gemm<4, 5><<<dim3(DI / 128, NTOK / 128), 256, gemm_smem(128)>>>(
        NTOK, DI, DTR, DTR, dth, dtwh, (float*)dlh, DI, dt_proj_b, nullptr, 0);

    // 6) chunked selective scan -> ys fp16
    scanA_kernel<<<NC * 32, 128>>>(dlh, xch, xdb, A_log, qb, sumdlb);
    scanB_kernel<<<NCH / 128, 128>>>(qb, sumdlb, A_log, hsb);
    scanC_kernel<<<NC * 32, 128>>>(dlh, xch, xzh, xdb, A_log, D_param, hsb, ysh);

    // 7) out_proj + residual (BN=64 tiles -> 512 balanced CTAs)
    hmma_gemm<2, 2><<<dim3(DM / 64, NTOK / 128), 128, gemm_smem(64)>>>(
        NTOK, DM, DI, DI, ysh, opwh, out, DM, nullptr, x, DM);
}

// round 16
// speedup vs baseline: 1.0015x; 1.0015x over previous
#include <cuda_runtime.h>
#include <cuda_fp16.h>
#include <cstdint>
#include <math.h>

// ---------------------------------------------------------------------------
// Problem constants
// ---------------------------------------------------------------------------
#define DM    1024
#define DI    2048
#define DS    16
#define DTR   64
#define NB    2
#define LL    2048
#define NTOK  (NB*LL)       // 4096
#define XZC   (2*DI)        // 4096
#define XDBC  (DTR+2*DS)    // 96
#define XPS   8             // x_proj split-K factor
#define NCH   (NB*DI)       // 4096 scan channels
#define CL    128           // scan chunk length
#define NC    (LL/CL)       // 16 chunks

// ---------------------------------------------------------------------------
// Base-ISA helpers (sm_80+; no 'a'-gated instructions)
// ---------------------------------------------------------------------------
__device__ __forceinline__ uint32_t smem_u32(const void* p) {
    uint32_t a;
    asm("{ .reg .u64 t; cvta.to.shared.u64 t, %1; cvt.u32.u64 %0, t; }" : "=r"(a) : "l"(p));
    return a;
}
__device__ __forceinline__ void cp_async16(uint32_t sa, const void* gp) {
    asm volatile("cp.async.cg.shared.global [%0], [%1], 16;" :: "r"(sa), "l"(gp));
}
__device__ __forceinline__ void cp_commit() {
    asm volatile("cp.async.commit_group;" ::: "memory");
}
template<int N>
__device__ __forceinline__ void cp_wait() {
    asm volatile("cp.async.wait_group %0;" :: "n"(N) : "memory");
}
__device__ __forceinline__ void ldsm_x4(uint32_t* r, uint32_t addr) {
    asm volatile("ldmatrix.sync.aligned.m8n8.x4.shared.b16 {%0,%1,%2,%3}, [%4];"
        : "=r"(r[0]), "=r"(r[1]), "=r"(r[2]), "=r"(r[3]) : "r"(addr));
}
__device__ __forceinline__ void mma_fp16(float* c, const uint32_t* a, const uint32_t* b) {
    asm volatile("mma.sync.aligned.m16n8k16.row.col.f32.f16.f16.f32 "
        "{%0,%1,%2,%3},{%4,%5,%6,%7},{%8,%9},{%0,%1,%2,%3};"
        : "+f"(c[0]), "+f"(c[1]), "+f"(c[2]), "+f"(c[3])
        : "r"(a[0]), "r"(a[1]), "r"(a[2]), "r"(a[3]), "r"(b[0]), "r"(b[1]));
}
__device__ __forceinline__ float softplus_f(float v) {
    return (v > 20.f) ? v : log1pf(expf(v));
}
// dA powers: dA[n] = e^(n+1), e = exp(-dl) (fast path when A[n] = -(n+1))
__device__ __forceinline__ void dA_fast(float e, float* dA) {
    float e2 = e * e, e3 = e2 * e, e4 = e2 * e2, e8 = e4 * e4;
    dA[0] = e;        dA[1] = e2;       dA[2] = e3;       dA[3] = e4;
    dA[4] = e4 * e;   dA[5] = e4 * e2;  dA[6] = e4 * e3;  dA[7] = e8;
    dA[8] = e8 * e;   dA[9] = e8 * e2;  dA[10] = e8 * e3; dA[11] = e8 * e4;
    dA[12] = e8 * dA[4]; dA[13] = e8 * dA[5]; dA[14] = e8 * dA[6]; dA[15] = e8 * e8;
}

// ---------------------------------------------------------------------------
// Scratch (device globals)
// ---------------------------------------------------------------------------
__device__ __align__(16) __half g_xnh[(size_t)NTOK*DM];
__device__ __align__(16) __half g_w1h[(size_t)XZC*DM];
__device__ __align__(16) __half g_xz[(size_t)NTOK*XZC];
__device__ __align__(16) __half g_xch[(size_t)NTOK*DI];
__device__ __align__(16) __half g_xpwh[(size_t)XDBC*DI];
__device__ __align__(16) float  g_xdbp[(size_t)XPS*NTOK*XDBC];
__device__ __align__(16) float  g_xdb[(size_t)NTOK*XDBC];
__device__ __align__(16) __half g_dth[(size_t)NTOK*DTR];
__device__ __align__(16) __half g_dtwh[(size_t)DI*DTR];
__device__ __align__(16) __half g_dlh[(size_t)NTOK*DI];
__device__ __align__(16) __half g_ysh[(size_t)NTOK*DI];
__device__ __align__(16) __half g_opwh[(size_t)DM*DI];
__device__ __align__(16) float  g_q[(size_t)NC*NCH*DS];
__device__ __align__(16) float  g_sumdl[(size_t)NC*NCH];
__device__ __align__(16) float  g_hs[(size_t)NC*NCH*DS];

// ---------------------------------------------------------------------------
// Fused LayerNorm + weight converts, block-range dispatch:
// blocks [0, NTOK)        : LayerNorm for token = blockIdx.x -> xnh fp16
// blocks [NTOK, NTOK+WB)  : grid-stride f32->fp16 convert of 4 weight arrays
// The two halves are data-independent; LN traffic hides under convert DRAM.
// ---------------------------------------------------------------------------
#define WN1 (XZC*DM)
#define WN2 (XDBC*DI)
#define WN3 (DI*DTR)
#define WN4 (DM*DI)
#define WPAIRS ((WN1+WN2+WN3+WN4)/2)
#define WBLOCKS ((WPAIRS + 255) / 256)

__global__ void ln_whalf_kernel(
    const float* __restrict__ x, const float* __restrict__ w,
    const float* __restrict__ bb, __half* __restrict__ oh,
    const float* __restrict__ w1, __half* __restrict__ h1,
    const float* __restrict__ w2, __half* __restrict__ h2,
    const float* __restrict__ w3, __half* __restrict__ h3,
    const float* __restrict__ w4, __half* __restrict__ h4)
{
    if (blockIdx.x >= NTOK) {
        // ---- weight convert branch ----
        int i = ((blockIdx.x - NTOK) * 256 + threadIdx.x) * 2;
        const float* ws; __half* hs; int off;
        if (i < WN1)                 { ws = w1; hs = h1; off = i; }
        else if (i < WN1+WN2)        { ws = w2; hs = h2; off = i - WN1; }
        else if (i < WN1+WN2+WN3)    { ws = w3; hs = h3; off = i - WN1 - WN2; }
        else if (i < WN1+WN2+WN3+WN4){ ws = w4; hs = h4; off = i - WN1 - WN2 - WN3; }
        else return;
        float2 v = *(const float2*)(ws + off);
        *(__half2*)(hs + off) = __floats2half2_rn(v.x, v.y);
        return;
    }
    // ---- LayerNorm branch ----
    int t = blockIdx.x;
    const int d4 = threadIdx.x * 4;
    float4 v = *(const float4*)(x + (size_t)t * DM + d4);
    float s  = v.x + v.y + v.z + v.w;
    float s2 = v.x * v.x + v.y * v.y + v.z * v.z + v.w * v.w;
#pragma unroll
    for (int o = 16; o > 0; o >>= 1) {
        s  += __shfl_xor_sync(0xffffffffu, s,  o);
        s2 += __shfl_xor_sync(0xffffffffu, s2, o);
    }
    __shared__ float rs[8], rs2[8];
    int wid = threadIdx.x >> 5, lid = threadIdx.x & 31;
    if (lid == 0) { rs[wid] = s; rs2[wid] = s2; }
    __syncthreads();
    if (wid == 0) {
        float a  = (lid < 8) ? rs[lid]  : 0.f;
        float a2 = (lid < 8) ? rs2[lid] : 0.f;
#pragma unroll
        for (int o = 4; o > 0; o >>= 1) {
            a  += __shfl_xor_sync(0xffffffffu, a,  o);
            a2 += __shfl_xor_sync(0xffffffffu, a2, o);
        }
        if (lid == 0) { rs[0] = a; rs2[0] = a2; }
    }
    __syncthreads();
    float mu = rs[0] * (1.f / DM);
    float var = rs2[0] * (1.f / DM) - mu * mu;
    float rstd = rsqrtf(var + 1e-5f);
    float4 wv = *(const float4*)(w + d4);
    float4 bv = *(const float4*)(bb + d4);
    float y0 = (v.x - mu) * rstd * wv.x + bv.x;
    float y1 = (v.y - mu) * rstd * wv.y + bv.y;
    float y2 = (v.z - mu) * rstd * wv.z + bv.z;
    float y3 = (v.w - mu) * rstd * wv.w + bv.w;
    __half2* op = (__half2*)(oh + (size_t)t * DM + d4);
    op[0] = __floats2half2_rn(y0, y1);
    op[1] = __floats2half2_rn(y2, y3);
}

// ---------------------------------------------------------------------------
// fp16 HMMA GEMM: CTA 128 x BN (BN = NWN*32), warp tile 64x32, K-chunks 64,
// triple-buffered cp.async, SMEM rows 144 B, B via ldsm_x4 pairs.
// Optional split-K via gridDim.z.
// EPI: 0 plain f32, 2 +resid f32, 4 fp16 out, 5 softplus(+bias) fp16 out
// ---------------------------------------------------------------------------
template<int NWN, int EPI>
__global__ void __launch_bounds__(64 * NWN, 2) hmma_gemm(
    int M, int N, int Ktot, int Kper,
    const __half* __restrict__ A, const __half* __restrict__ B,
    float* __restrict__ C, int ldc,
    const float* __restrict__ bias,
    const float* __restrict__ resid, int ldr)
{
    constexpr int BN      = NWN * 32;
    constexpr int THREADS = 64 * NWN;
    constexpr int RSTRIDE = 144;
    constexpr int AB      = 128 * RSTRIDE;
    constexpr int BB      = BN * RSTRIDE;
    constexpr int BUF     = AB + BB;

    extern __shared__ char smraw[];
    const uint32_t sbase = smem_u32(smraw);

    const int tid  = threadIdx.x;
    const int lane = tid & 31;
    const int wid  = tid >> 5;
    const int warp_m = wid / NWN;
    const int warp_n = wid % NWN;
    const int bm = blockIdx.y * 128;
    const int bn = blockIdx.x * BN;
    const int kbase = blockIdx.z * Kper;
    const int KC = Kper >> 6;
    float* Cz = C + (size_t)blockIdx.z * M * ldc;

    float acc[4][4][4];
#pragma unroll
    for (int i = 0; i < 4; i++)
#pragma unroll
        for (int j = 0; j < 4; j++)
#pragma unroll
            for (int q = 0; q < 4; q++) acc[i][j][q] = 0.f;

    auto load_chunk = [&](int c, int b) {
        const int koff = kbase + c * 64;
        const uint32_t bbase = sbase + (uint32_t)b * BUF;
        for (int i = tid; i < 1024; i += THREADS) {          // A: 128 rows x 8 segs
            int row = i >> 3, seg = i & 7;
            cp_async16(bbase + row * RSTRIDE + seg * 16,
                       A + (size_t)(bm + row) * Ktot + koff + seg * 8);
        }
        for (int i = tid; i < BN * 8; i += THREADS) {        // B: BN rows x 8 segs
            int row = i >> 3, seg = i & 7;
            cp_async16(bbase + AB + row * RSTRIDE + seg * 16,
                       B + (size_t)(bn + row) * Ktot + koff + seg * 8);
        }
        cp_commit();
    };

    load_chunk(0, 0);
    if (KC > 1) load_chunk(1, 1);

    for (int c = 0; c < KC; c++) {
        if (c + 2 < KC) { load_chunk(c + 2, (c + 2) % 3); cp_wait<2>(); }
        else if (c + 1 < KC) { cp_wait<1>(); }
        else { cp_wait<0>(); }
        __syncthreads();

        const uint32_t bbase = sbase + (uint32_t)(c % 3) * BUF;
#pragma unroll
        for (int ks = 0; ks < 4; ks++) {
            uint32_t ah[4][4], bh[4][2];
            const uint32_t a_lane = (uint32_t)((warp_m * 64 + (lane & 15)) * RSTRIDE
                                               + ks * 32 + (lane >> 4) * 16);
#pragma unroll
            for (int mi = 0; mi < 4; mi++)
                ldsm_x4(ah[mi], bbase + a_lane + mi * 16 * RSTRIDE);
            // B: one ldsm_x4 covers two n8 tiles (lanes 16-31 -> rows +8)
            const uint32_t b_lane = (uint32_t)((warp_n * 32 + ((lane >> 4) & 1) * 8 + (lane & 7)) * RSTRIDE
                                               + ks * 32 + ((lane >> 3) & 1) * 16);
#pragma unroll
            for (int nj = 0; nj < 2; nj++) {
                uint32_t r4[4];
                ldsm_x4(r4, bbase + AB + b_lane + nj * 16 * RSTRIDE);
                bh[2 * nj][0] = r4[0]; bh[2 * nj][1] = r4[1];
                bh[2 * nj + 1][0] = r4[2]; bh[2 * nj + 1][1] = r4[3];
            }
#pragma unroll
            for (int mi = 0; mi < 4; mi++)
#pragma unroll
                for (int ni = 0; ni < 4; ni++)
                    mma_fp16(acc[mi][ni], ah[mi], bh[ni]);
        }
        __syncthreads();
    }

#pragma unroll
    for (int mi = 0; mi < 4; mi++)
#pragma unroll
        for (int ni = 0; ni < 4; ni++) {
            float* cc = acc[mi][ni];
            const int m0 = bm + warp_m * 64 + mi * 16 + (lane >> 2);
            const int n0 = bn + warp_n * 32 + ni * 8 + (lane & 3) * 2;
#pragma unroll
            for (int half = 0; half < 2; half++) {
                const int m = m0 + half * 8;
                float v0 = cc[half * 2], v1 = cc[half * 2 + 1];
                if (EPI == 5) { v0 = softplus_f(v0 + bias[n0]); v1 = softplus_f(v1 + bias[n0 + 1]); }
                if (EPI == 2) {
                    const float2 r2 = *(const float2*)(resid + (size_t)m * ldr + n0);
                    v0 += r2.x; v1 += r2.y;
                }
                if (EPI == 4 || EPI == 5) {
                    __half* Ch = (__half*)Cz;
                    *(__half2*)(Ch + (size_t)m * ldc + n0) = __floats2half2_rn(v0, v1);
                } else {
                    *(float2*)(Cz + (size_t)m * ldc + n0) = make_float2(v0, v1);
                }
            }
        }
}

// ---------------------------------------------------------------------------
// x_proj split-K reduce: xdb = sum_z partials; also emit dt (cols 0..63) fp16
// ---------------------------------------------------------------------------
__global__ void xdb_reduce_kernel(const float* __restrict__ part, float* __restrict__ xdb,
                                  __half* __restrict__ dth)
{
    int idx = blockIdx.x * 256 + threadIdx.x;
    if (idx >= NTOK * XDBC) return;
    float s = 0.f;
#pragma unroll
    for (int z = 0; z < XPS; z++) s += part[(size_t)z * NTOK * XDBC + idx];
    xdb[idx] = s;
    int n = idx % XDBC;
    if (n < DTR) {
        int m = idx / XDBC;
        dth[(size_t)m * DTR + n] = __float2half_rn(s);
    }
}

// ---------------------------------------------------------------------------
// Depthwise causal conv (k=4) + bias + SiLU.
// Each thread: 2 adjacent channels x 8 consecutive timesteps -> 11 half2
// loads produce 8 half2 outputs (1.375 loads/output).
// ---------------------------------------------------------------------------
__global__ void conv_silu_kernel(const __half* __restrict__ xz, const float* __restrict__ cw,
                                 const float* __restrict__ cb, __half* __restrict__ oh)
{
    int idx = blockIdx.x * blockDim.x + threadIdx.x;   // NTOK*DI/16 threads
    int dp = idx & (DI / 2 - 1);
    int d  = dp * 2;
    int tg = idx >> 10;
    int t0 = (tg & (LL / 8 - 1)) * 8;
    int b  = tg >> 8;                                  // LL/8 = 256

    float4 wa = *(const float4*)(cw + d * 4);
    float4 wb = *(const float4*)(cw + d * 4 + 4);
    float2 bias2 = *(const float2*)(cb + d);

    const __half* col = xz + (size_t)b * LL * XZC + d;
    float2 v[11];
#pragma unroll
    for (int k = 0; k < 11; k++) {
        int t = t0 + k - 3;
        v[k] = (t >= 0) ? __half22float2(*(const __half2*)(col + (size_t)t * XZC))
                        : make_float2(0.f, 0.f);
    }
#pragma unroll
    for (int i = 0; i < 8; i++) {
        float a0 = bias2.x, a1 = bias2.y;
        a0 = fmaf(v[i].x,     wa.x, a0); a1 = fmaf(v[i].y,     wb.x, a1);
        a0 = fmaf(v[i + 1].x, wa.y, a0); a1 = fmaf(v[i + 1].y, wb.y, a1);
        a0 = fmaf(v[i + 2].x, wa.z, a0); a1 = fmaf(v[i + 2].y, wb.z, a1);
        a0 = fmaf(v[i + 3].x, wa.w, a0); a1 = fmaf(v[i + 3].y, wb.w, a1);
        float r0 = a0 * __fdividef(1.f, 1.f + __expf(-a0));
        float r1 = a1 * __fdividef(1.f, 1.f + __expf(-a1));
        *(__half2*)(oh + ((size_t)b * LL + t0 + i) * DI + d) = __floats2half2_rn(r0, r1);
    }
}

// ---------------------------------------------------------------------------
// Chunked scan, phase A: per chunk, local scan with h0=0 -> q, sum(delta).
// ---------------------------------------------------------------------------
__global__ void __launch_bounds__(128) scanA_kernel(
    const __half* __restrict__ delta, const __half* __restrict__ u,
    const float* __restrict__ xdb, const float* __restrict__ A_log,
    float* __restrict__ q, float* __restrict__ sumdl)
{
    const int tc = blockIdx.x & 15;
    const int g  = blockIdx.x >> 4;
    const int b  = g >> 4;
    const int d0 = (g & 15) << 7;
    const int tid = threadIdx.x;
    const int d = d0 + tid;

    float An[DS];
    bool fast = true;
#pragma unroll
    for (int n = 0; n < DS; n++) {
        An[n] = -expf(A_log[d * DS + n]);
        fast = fast && (fabsf(An[n] + (float)(n + 1)) < 1e-4f * (float)(n + 1));
    }
    float h[DS];
#pragma unroll
    for (int n = 0; n < DS; n++) h[n] = 0.f;
    float sdl = 0.f;

    const size_t base_u  = (size_t)b * LL * DI + d0 + tid;
    const size_t base_bc = (size_t)b * LL * XDBC + DTR;
    const int t0 = tc * CL;

    __shared__ float sB[32][DS];
    for (int tile = 0; tile < CL / 32; tile++) {
        __syncthreads();
        for (int i = tid; i < 32 * DS; i += 128) {
            int s = i >> 4, j = i & 15;
            sB[s][j] = xdb[base_bc + (size_t)(t0 + tile * 32 + s) * XDBC + j];
        }
        __syncthreads();
#pragma unroll 2
        for (int s = 0; s < 32; s++) {
            const int t = t0 + tile * 32 + s;
            float dl = __half2float(delta[base_u + (size_t)t * DI]);
            float ut = __half2float(u[base_u + (size_t)t * DI]);
            sdl += dl;
            float dA[DS];
            if (fast) { dA_fast(__expf(-dl), dA); }
            else {
#pragma unroll
                for (int n = 0; n < DS; n++) dA[n] = __expf(dl * An[n]);
            }
            float w = dl * ut;
#pragma unroll
            for (int n = 0; n < DS; n++)
                h[n] = fmaf(dA[n], h[n], w * sB[s][n]);
        }
    }
    const int bd = b * DI + d;
    float* qp = q + ((size_t)tc * NCH + bd) * DS;
#pragma unroll
    for (int n = 0; n < DS; n += 4)
        *(float4*)(qp + n) = make_float4(h[n], h[n + 1], h[n + 2], h[n + 3]);
    sumdl[tc * NCH + bd] = sdl;
}

// ---------------------------------------------------------------------------
// Chunked scan, phase B: serial prefix over 16 chunks -> h_start per chunk.
// ---------------------------------------------------------------------------
__global__ void __launch_bounds__(128) scanB_kernel(
    const float* __restrict__ q, const float* __restrict__ sumdl,
    const float* __restrict__ A_log, float* __restrict__ hs)
{
    const int bd = blockIdx.x * 128 + threadIdx.x;
    const int d = bd & (DI - 1);

    float An[DS];
    bool fast = true;
#pragma unroll
    for (int n = 0; n < DS; n++) {
        An[n] = -expf(A_log[d * DS + n]);
        fast = fast && (fabsf(An[n] + (float)(n + 1)) < 1e-4f * (float)(n + 1));
    }
    float h[DS];
#pragma unroll
    for (int n = 0; n < DS; n++) h[n] = 0.f;

    for (int c = 0; c < NC; c++) {
        float* hp = hs + ((size_t)c * NCH + bd) * DS;
#pragma unroll
        for (int n = 0; n < DS; n += 4)
            *(float4*)(hp + n) = make_float4(h[n], h[n + 1], h[n + 2], h[n + 3]);
        if (c == NC - 1) break;
        float sdl = sumdl[c * NCH + bd];
        float P[DS];
        if (fast) { dA_fast(__expf(-sdl), P); }
        else {
#pragma unroll
            for (int n = 0; n < DS; n++) P[n] = __expf(An[n] * sdl);
        }
        const float* qp = q + ((size_t)c * NCH + bd) * DS;
#pragma unroll
        for (int n = 0; n < DS; n++)
            h[n] = fmaf(P[n], h[n], qp[n]);
    }
}

// ---------------------------------------------------------------------------
// Chunked scan, phase C: re-scan with correct h_start, gate with silu(z).
// ---------------------------------------------------------------------------
__global__ void __launch_bounds__(128) scanC_kernel(
    const __half* __restrict__ delta, const __half* __restrict__ u,
    const __half* __restrict__ xz, const float* __restrict__ xdb,
    const float* __restrict__ A_log, const float* __restrict__ Dp,
    const float* __restrict__ hs, __half* __restrict__ ysh)
{
    const int tc = blockIdx.x & 15;
    const int g  = blockIdx.x >> 4;
    const int b  = g >> 4;
    const int d0 = (g & 15) << 7;
    const int tid = threadIdx.x;
    const int d = d0 + tid;

    float An[DS];
    bool fast = true;
#pragma unroll
    for (int n = 0; n < DS; n++) {
        An[n] = -expf(A_log[d * DS + n]);
        fast = fast && (fabsf(An[n] + (float)(n + 1)) < 1e-4f * (float)(n + 1));
    }
    float Dd = Dp[d];
    const int bd = b * DI + d;
    float h[DS];
    {
        const float* hp = hs + ((size_t)tc * NCH + bd) * DS;
#pragma unroll
        for (int n = 0; n < DS; n += 4) {
            float4 v = *(const float4*)(hp + n);
            h[n] = v.x; h[n + 1] = v.y; h[n + 2] = v.z; h[n + 3] = v.w;
        }
    }

    const size_t base_u  = (size_t)b * LL * DI + d0 + tid;
    const size_t base_z  = (size_t)b * LL * XZC + DI + d0 + tid;
    const size_t base_bc = (size_t)b * LL * XDBC + DTR;
    const int t0 = tc * CL;

    __shared__ float sBC[32][2 * DS];
    for (int tile = 0; tile < CL / 32; tile++) {
        __syncthreads();
        for (int i = tid; i < 32 * 2 * DS; i += 128) {
            int s = i >> 5, j = i & 31;
            sBC[s][j] = xdb[base_bc + (size_t)(t0 + tile * 32 + s) * XDBC + j];
        }
        __syncthreads();
#pragma unroll 2
        for (int s = 0; s < 32; s++) {
            const int t = t0 + tile * 32 + s;
            float dl = __half2float(delta[base_u + (size_t)t * DI]);
            float ut = __half2float(u[base_u + (size_t)t * DI]);
            float zt = __half2float(xz[base_z + (size_t)t * XZC]);
            float dA[DS];
            if (fast) { dA_fast(__expf(-dl), dA); }
            else {
#pragma unroll
                for (int n = 0; n < DS; n++) dA[n] = __expf(dl * An[n]);
            }
            float w = dl * ut;
#pragma unroll
            for (int n = 0; n < DS; n++)
                h[n] = fmaf(dA[n], h[n], w * sBC[s][n]);

            float y0 = 0.f, y1 = 0.f, y2 = 0.f, y3 = 0.f;
#pragma unroll
            for (int n = 0; n < DS; n += 4) {
                y0 = fmaf(h[n],     sBC[s][DS + n],     y0);
                y1 = fmaf(h[n + 1], sBC[s][DS + n + 1], y1);
                y2 = fmaf(h[n + 2], sBC[s][DS + n + 2], y2);
                y3 = fmaf(h[n + 3], sBC[s][DS + n + 3], y3);
            }
            float y = (y0 + y1) + (y2 + y3) + ut * Dd;
            float sig = __fdividef(1.f, 1.f + __expf(-zt));
            ysh[base_u + (size_t)t * DI] = __float2half_rn(y * zt * sig);
        }
    }
}

// ---------------------------------------------------------------------------
// Launch sequence
// ---------------------------------------------------------------------------
static inline int gemm_smem(int BN) { return 3 * (128 + BN) * 144; }

extern "C" void kernel_launch(void* const* d_in, const int* in_sizes, int n_in,
                              void* d_out, int out_size)
{
    const float* x         = (const float*)d_in[0];
    const float* norm_w    = (const float*)d_in[1];
    const float* norm_b    = (const float*)d_in[2];
    const float* in_proj_w = (const float*)d_in[3];
    const float* conv_w    = (const float*)d_in[4];
    const float* conv_b    = (const float*)d_in[5];
    const float* x_proj_w  = (const float*)d_in[6];
    const float* dt_proj_w = (const float*)d_in[7];
    const float* dt_proj_b = (const float*)d_in[8];
    const float* A_log     = (const float*)d_in[9];
    const float* D_param   = (const float*)d_in[10];
    const float* out_proj_w= (const float*)d_in[11];
    float* out = (float*)d_out;

    __half *xnh, *w1h, *xzh, *xch, *xpwh, *dth, *dtwh, *dlh, *ysh, *opwh;
    float *xdbp, *xdb, *qb, *sumdlb, *hsb;
    cudaGetSymbolAddress((void**)&xnh, g_xnh);
    cudaGetSymbolAddress((void**)&w1h, g_w1h);
    cudaGetSymbolAddress((void**)&xzh, g_xz);
    cudaGetSymbolAddress((void**)&xch, g_xch);
    cudaGetSymbolAddress((void**)&xpwh, g_xpwh);
    cudaGetSymbolAddress((void**)&xdbp, g_xdbp);
    cudaGetSymbolAddress((void**)&xdb, g_xdb);
    cudaGetSymbolAddress((void**)&dth, g_dth);
    cudaGetSymbolAddress((void**)&dtwh, g_dtwh);
    cudaGetSymbolAddress((void**)&dlh, g_dlh);
    cudaGetSymbolAddress((void**)&ysh, g_ysh);
    cudaGetSymbolAddress((void**)&opwh, g_opwh);
    cudaGetSymbolAddress((void**)&qb, g_q);
    cudaGetSymbolAddress((void**)&sumdlb, g_sumdl);
    cudaGetSymbolAddress((void**)&hsb, g_hs);

    cudaFuncSetAttribute(hmma_gemm<4, 4>, cudaFuncAttributeMaxDynamicSharedMemorySize, gemm_smem(128));
    cudaFuncSetAttribute(hmma_gemm<4, 5>, cudaFuncAttributeMaxDynamicSharedMemorySize, gemm_smem(128));
    cudaFuncSetAttribute(hmma_gemm<2, 2>, cudaFuncAttributeMaxDynamicSharedMemorySize, gemm_smem(64));
    cudaFuncSetAttribute(hmma_gemm<3, 0>, cudaFuncAttributeMaxDynamicSharedMemorySize, gemm_smem(96));

    // 0+1) fused LayerNorm (blocks 0..NTOK-1) + weight converts (rest)
    ln_whalf_kernel<<<NTOK + WBLOCKS, 256>>>(
        x, norm_w, norm_b, xnh,
        in_proj_w, w1h, x_proj_w, xpwh, dt_proj_w, dtwh, out_proj_w, opwh);

    // 2) in_proj: xz(fp16)[4096,4096] = xn @ in_proj_w^T (BN=128)
    hmma_gemm<4, 4><<<dim3(XZC / 128, NTOK / 128), 256, gemm_smem(128)>>>(
        NTOK, XZC, DM, DM, xnh, w1h, (float*)xzh, XZC, nullptr, nullptr, 0);

    // 3) conv + SiLU -> xch fp16 (2 channels x 8 timesteps per thread)
    conv_silu_kernel<<<(NTOK * DI / 16) / 256, 256>>>(xzh, conv_w, conv_b, xch);

    // 4) x_proj (split-K x8): partials, then reduce (+ dt fp16)
    hmma_gemm<3, 0><<<dim3(1, NTOK / 128, XPS), 192, gemm_smem(96)>>>(
        NTOK, XDBC, DI, DI / XPS, xch, xpwh, xdbp, XDBC, nullptr, nullptr, 0);
    xdb_reduce_kernel<<<(NTOK * XDBC + 255) / 256, 256>>>(xdbp, xdb, dth);

    // 5) dt_proj + softplus -> delta fp16
    hmma_gemm<4, 5><<<dim3(DI / 128, NTOK / 128), 256, gemm_smem(128)>>>(
        NTOK, DI, DTR, DTR, dth, dtwh, (float*)dlh, DI, dt_proj_b, nullptr, 0);

    // 6) chunked selective scan -> ys fp16
    scanA_kernel<<<NC * 32, 128>>>(dlh, xch, xdb, A_log, qb, sumdlb);
    scanB_kernel<<<NCH / 128, 128>>>(qb, sumdlb, A_log, hsb);
    scanC_kernel<<<NC * 32, 128>>>(dlh, xch, xzh, xdb, A_log, D_param, hsb, ysh);

    // 7) out_proj + residual (BN=64 tiles -> 512 balanced CTAs)
    hmma_gemm<2, 2><<<dim3(DM / 64, NTOK / 128), 128, gemm_smem(64)>>>(
        NTOK, DM, DI, DI, ysh, opwh, out, DM, nullptr, x, DM);
}